// round 14
// baseline (speedup 1.0000x reference)
#include <cuda_runtime.h>
#include <cstdint>

#define L_SEQ   2048
#define D_DIM   64
#define TILE    128
#define R_BAND  128
#define NTILE   16
#define ZDIM    32               // B*H
#define KT_S    132              // Kt row stride in floats (128 + pad)

#define N_BAND_PER_Z 46
#define Z_PER_CHUNK  4
#define N_CHUNKS     (ZDIM / Z_PER_CHUNK)                 // 8
#define BAND_BLOCKS_PER_CHUNK (N_BAND_PER_Z * Z_PER_CHUNK) // 184

#define FILL_CTAS    512
#define FILL_THREADS 256
#define FILL_ITERS   32          // 512*256*32 float4 = 64 MB per chunk

typedef unsigned long long ull;

__device__ __forceinline__ void fma2(ull& d, ull a, ull b)
{
    asm("fma.rn.f32x2 %0, %1, %2, %0;" : "+l"(d) : "l"(a), "l"(b));
}

__device__ __forceinline__ ull dup2(float v)
{
    ull r;
    asm("mov.b64 %0, {%1, %1};" : "=l"(r) : "f"(v));
    return r;
}

__device__ __forceinline__ float2 unpack2(ull v)
{
    float2 f;
    asm("mov.b64 {%0, %1}, %2;" : "=f"(f.x), "=f"(f.y) : "l"(v));
    return f;
}

// ================== linear zero-fill kernel (memset-shaped) ==================
__global__ __launch_bounds__(FILL_THREADS)
void zero_fill_linear(float4* __restrict__ dst)
{
    const float4 z = make_float4(0.f, 0.f, 0.f, 0.f);
    size_t i = (size_t)blockIdx.x * FILL_THREADS + threadIdx.x;
    const size_t stride = (size_t)FILL_CTAS * FILL_THREADS;
    #pragma unroll 8
    for (int k = 0; k < FILL_ITERS; ++k)
        dst[i + (size_t)k * stride] = z;
}

// ===================== band kernel (R13 band path + z0) =====================
extern __shared__ float4 smem4[];

__global__ __launch_bounds__(256, 2)
void band_scores_kernel(const float* __restrict__ Q,
                        const float* __restrict__ K,
                        float* __restrict__ out,
                        int z0)
{
    const int bid = blockIdx.x;
    const int tid = threadIdx.x;

    const int z = z0 + bid / N_BAND_PER_Z;
    const int n = bid % N_BAND_PER_Z;          // 0..45
    const int ti = (n + 1) / 3;
    const int tj = ti - 1 + ((n + 1) % 3);

    float* outTile = out + ((size_t)z * L_SEQ + (size_t)ti * TILE) * L_SEQ
                         + (size_t)tj * TILE;

    float4* Qs4 = smem4;                              // [128][16] swizzled
    float*  Kt  = (float*)(smem4 + TILE * 16);        // [64][KT_S] transposed

    const float* Qg = Q + ((size_t)z * L_SEQ + (size_t)ti * TILE) * D_DIM;
    const float* Kg = K + ((size_t)z * L_SEQ + (size_t)tj * TILE) * D_DIM;

    #pragma unroll
    for (int p = 0; p < 8; ++p) {
        int idx = tid + p * 256;
        int row = idx >> 4;
        int kq  = idx & 15;
        Qs4[row * 16 + (kq ^ ((row >> 3) & 7))] = ((const float4*)Qg)[idx];
    }
    #pragma unroll
    for (int p = 0; p < 8; ++p) {
        int idx = tid + p * 256;
        int c   = idx >> 4;
        int kq  = idx & 15;
        float4 v = ((const float4*)Kg)[idx];
        float* dst = &Kt[(4 * kq) * KT_S + c];
        dst[0 * KT_S] = v.x;
        dst[1 * KT_S] = v.y;
        dst[2 * KT_S] = v.z;
        dst[3 * KT_S] = v.w;
    }
    __syncthreads();

    const int ty  = tid >> 4;
    const int tx  = tid & 15;
    const int qsw = ty & 7;

    ull acc2[8][4];
    #pragma unroll
    for (int r = 0; r < 8; ++r)
        #pragma unroll
        for (int p = 0; p < 4; ++p) acc2[r][p] = 0ULL;

    #pragma unroll 4
    for (int kq = 0; kq < 16; ++kq) {
        ulonglong2 bA[4], bB[4];
        #pragma unroll
        for (int j = 0; j < 4; ++j) {
            const float* base = &Kt[(4 * kq + j) * KT_S + 4 * tx];
            bA[j] = *(const ulonglong2*)base;
            bB[j] = *(const ulonglong2*)(base + 64);
        }
        #pragma unroll
        for (int r = 0; r < 8; ++r) {
            float4 qv = Qs4[(8 * ty + r) * 16 + (kq ^ qsw)];
            #pragma unroll
            for (int j = 0; j < 4; ++j) {
                float q = (j == 0) ? qv.x : (j == 1) ? qv.y
                        : (j == 2) ? qv.z : qv.w;
                ull q2 = dup2(q);
                fma2(acc2[r][0], q2, bA[j].x);
                fma2(acc2[r][1], q2, bA[j].y);
                fma2(acc2[r][2], q2, bB[j].x);
                fma2(acc2[r][3], q2, bB[j].y);
            }
        }
    }

    if (ti == tj) {
        #pragma unroll
        for (int r = 0; r < 8; ++r) {
            float* orow = outTile + (size_t)(8 * ty + r) * L_SEQ;
            float2 p0 = unpack2(acc2[r][0]);
            float2 p1 = unpack2(acc2[r][1]);
            float2 p2 = unpack2(acc2[r][2]);
            float2 p3 = unpack2(acc2[r][3]);
            ((float4*)orow)[tx]        = make_float4(p0.x, p0.y, p1.x, p1.y);
            ((float4*)(orow + 64))[tx] = make_float4(p2.x, p2.y, p3.x, p3.y);
        }
        return;
    }

    // |ti-tj| == 1: partial band, mask per element
    const int gi0 = ti * TILE + 8 * ty;
    const int jA0 = tj * TILE + 4 * tx;
    const int jB0 = tj * TILE + 64 + 4 * tx;

    #pragma unroll
    for (int r = 0; r < 8; ++r) {
        const int gi = gi0 + r;
        float* orow = outTile + (size_t)(8 * ty + r) * L_SEQ;

        float2 p0 = unpack2(acc2[r][0]);
        float2 p1 = unpack2(acc2[r][1]);
        float2 p2 = unpack2(acc2[r][2]);
        float2 p3 = unpack2(acc2[r][3]);

        float4 vA, vB;
        {
            int d0 = gi - (jA0 + 0); if (d0 < 0) d0 = -d0;
            int d1 = gi - (jA0 + 1); if (d1 < 0) d1 = -d1;
            int d2 = gi - (jA0 + 2); if (d2 < 0) d2 = -d2;
            int d3 = gi - (jA0 + 3); if (d3 < 0) d3 = -d3;
            vA.x = (d0 <= R_BAND) ? p0.x : 0.f;
            vA.y = (d1 <= R_BAND) ? p0.y : 0.f;
            vA.z = (d2 <= R_BAND) ? p1.x : 0.f;
            vA.w = (d3 <= R_BAND) ? p1.y : 0.f;
        }
        {
            int d0 = gi - (jB0 + 0); if (d0 < 0) d0 = -d0;
            int d1 = gi - (jB0 + 1); if (d1 < 0) d1 = -d1;
            int d2 = gi - (jB0 + 2); if (d2 < 0) d2 = -d2;
            int d3 = gi - (jB0 + 3); if (d3 < 0) d3 = -d3;
            vB.x = (d0 <= R_BAND) ? p2.x : 0.f;
            vB.y = (d1 <= R_BAND) ? p2.y : 0.f;
            vB.z = (d2 <= R_BAND) ? p3.x : 0.f;
            vB.w = (d3 <= R_BAND) ? p3.y : 0.f;
        }

        ((float4*)orow)[tx]        = vA;
        ((float4*)(orow + 64))[tx] = vB;
    }
}

extern "C" void kernel_launch(void* const* d_in, const int* in_sizes, int n_in,
                              void* d_out, int out_size)
{
    const float* Q  = (const float*)d_in[0];
    const float* K  = (const float*)d_in[1];
    float*       out = (float*)d_out;

    const int smem_bytes = TILE * 16 * 16 + 64 * KT_S * 4;  // 66560

    cudaFuncSetAttribute(band_scores_kernel,
                         cudaFuncAttributeMaxDynamicSharedMemorySize,
                         smem_bytes);

    // Pipelined overwrite: fill chunk c (linear memset-style, side stream)
    // -> event -> band chunk c (main stream). Fill c+1 overlaps band c.
    // Streams/events are created per call and intentionally leaked (R13
    // precedent: capture-safe; kernel_launch runs only twice outside timing).
    cudaStream_t s2;
    cudaStreamCreateWithFlags(&s2, cudaStreamNonBlocking);

    cudaEvent_t e_fork;
    cudaEventCreateWithFlags(&e_fork, cudaEventDisableTiming);
    cudaEventRecord(e_fork, 0);
    cudaStreamWaitEvent(s2, e_fork, 0);

    const size_t chunk_floats = (size_t)Z_PER_CHUNK * L_SEQ * L_SEQ; // 16.78M

    for (int c = 0; c < N_CHUNKS; ++c) {
        zero_fill_linear<<<FILL_CTAS, FILL_THREADS, 0, s2>>>(
            (float4*)(out + c * chunk_floats));

        cudaEvent_t e;
        cudaEventCreateWithFlags(&e, cudaEventDisableTiming);
        cudaEventRecord(e, s2);
        cudaStreamWaitEvent(0, e, 0);    // band chunk c waits its fill

        band_scores_kernel<<<BAND_BLOCKS_PER_CHUNK, 256, smem_bytes>>>(
            Q, K, out, c * Z_PER_CHUNK);
    }
    // main stream's last band kernel already depends on the last fill;
    // all work joins on the capture (main) stream.
}

// round 16
// speedup vs baseline: 1.3856x; 1.3856x over previous
#include <cuda_runtime.h>
#include <cstdint>

#define L_SEQ   2048
#define D_DIM   64
#define TILE    128
#define R_BAND  128
#define NTILE   16
#define ZDIM    32               // B*H
#define KT_S    132              // Kt row stride in floats (128 + pad)

#define N_BAND_PER_Z 46
#define N_BAND   (N_BAND_PER_Z * ZDIM)   // 1472

#define FILL_CTAS  1024          // x 8 warps x 8 units = 65536 row-units
#define UNITS_PER_WARP 8

typedef unsigned long long ull;

__device__ __forceinline__ void fma2(ull& d, ull a, ull b)
{
    asm("fma.rn.f32x2 %0, %1, %2, %0;" : "+l"(d) : "l"(a), "l"(b));
}

__device__ __forceinline__ ull dup2(float v)
{
    ull r;
    asm("mov.b64 %0, {%1, %1};" : "=l"(r) : "f"(v));
    return r;
}

__device__ __forceinline__ float2 unpack2(ull v)
{
    float2 f;
    asm("mov.b64 {%0, %1}, %2;" : "=f"(f.x), "=f"(f.y) : "l"(v));
    return f;
}

// ============== fill kernel: memset-shaped STG over complement ==============
// Row-unit (z, s, r): merged zero span = suffix of row r + prefix of row r+1
// (contiguous, up to ~6.7 KB). Warp writes it 512 B per warp-instruction,
// ascending addresses — identical instruction pattern to a linear memset.
__global__ __launch_bounds__(256)
void zero_fill_stg(float* __restrict__ out)
{
    const int gw   = blockIdx.x * 8 + (threadIdx.x >> 5);  // 0..8191
    const int lane = threadIdx.x & 31;
    const float4 zz = make_float4(0.f, 0.f, 0.f, 0.f);

    #pragma unroll
    for (int k = 0; k < UNITS_PER_WARP; ++k) {
        const int ug = gw * UNITS_PER_WARP + k;   // 0..65535
        const int z  = ug >> 11;                  // 0..31
        const int u  = ug & 2047;
        const int s  = u >> 7;                    // stripe 0..15
        const int r  = u & 127;                   // row-unit 0..127

        const int lo = (s > 0)  ? s - 1 : 0;
        const int hi = (s < 15) ? s + 1 : 15;

        char* sbase = (char*)out + (size_t)z * L_SEQ * L_SEQ * 4
                                 + (size_t)s * TILE * 8192;

        if (r < 127) {
            const int n512 = (15 - hi) + lo;      // 512B units in merged span
            if (n512) {
                float4* q = (float4*)(sbase + (size_t)r * 8192
                                            + (size_t)(hi + 1) * 512);
                const int nf4 = n512 * 32;        // float4 count
                for (int i = lane; i < nf4; i += 32) q[i] = zz;
            }
        } else {
            if (hi < 15) {                        // suffix of row 127
                float4* q = (float4*)(sbase + (size_t)127 * 8192
                                            + (size_t)(hi + 1) * 512);
                const int nf4 = (15 - hi) * 32;
                for (int i = lane; i < nf4; i += 32) q[i] = zz;
            }
            if (lo > 0) {                         // prefix of row 0
                float4* q = (float4*)sbase;
                const int nf4 = lo * 32;
                for (int i = lane; i < nf4; i += 32) q[i] = zz;
            }
        }
    }
}

// ================== band kernel (byte-identical to R13) ==================
extern __shared__ float4 smem4[];

__global__ __launch_bounds__(256, 2)
void band_scores_kernel(const float* __restrict__ Q,
                        const float* __restrict__ K,
                        float* __restrict__ out)
{
    const int bid = blockIdx.x;
    const int tid = threadIdx.x;

    const int z = bid / N_BAND_PER_Z;
    const int n = bid - z * N_BAND_PER_Z;      // 0..45
    const int ti = (n + 1) / 3;
    const int tj = ti - 1 + ((n + 1) % 3);

    float* outTile = out + ((size_t)z * L_SEQ + (size_t)ti * TILE) * L_SEQ
                         + (size_t)tj * TILE;

    float4* Qs4 = smem4;                              // [128][16] swizzled
    float*  Kt  = (float*)(smem4 + TILE * 16);        // [64][KT_S] transposed

    const float* Qg = Q + ((size_t)z * L_SEQ + (size_t)ti * TILE) * D_DIM;
    const float* Kg = K + ((size_t)z * L_SEQ + (size_t)tj * TILE) * D_DIM;

    #pragma unroll
    for (int p = 0; p < 8; ++p) {
        int idx = tid + p * 256;
        int row = idx >> 4;
        int kq  = idx & 15;
        Qs4[row * 16 + (kq ^ ((row >> 3) & 7))] = ((const float4*)Qg)[idx];
    }
    #pragma unroll
    for (int p = 0; p < 8; ++p) {
        int idx = tid + p * 256;
        int c   = idx >> 4;
        int kq  = idx & 15;
        float4 v = ((const float4*)Kg)[idx];
        float* dst = &Kt[(4 * kq) * KT_S + c];
        dst[0 * KT_S] = v.x;
        dst[1 * KT_S] = v.y;
        dst[2 * KT_S] = v.z;
        dst[3 * KT_S] = v.w;
    }
    __syncthreads();

    const int ty  = tid >> 4;
    const int tx  = tid & 15;
    const int qsw = ty & 7;

    ull acc2[8][4];
    #pragma unroll
    for (int r = 0; r < 8; ++r)
        #pragma unroll
        for (int p = 0; p < 4; ++p) acc2[r][p] = 0ULL;

    #pragma unroll 4
    for (int kq = 0; kq < 16; ++kq) {
        ulonglong2 bA[4], bB[4];
        #pragma unroll
        for (int j = 0; j < 4; ++j) {
            const float* base = &Kt[(4 * kq + j) * KT_S + 4 * tx];
            bA[j] = *(const ulonglong2*)base;
            bB[j] = *(const ulonglong2*)(base + 64);
        }
        #pragma unroll
        for (int r = 0; r < 8; ++r) {
            float4 qv = Qs4[(8 * ty + r) * 16 + (kq ^ qsw)];
            #pragma unroll
            for (int j = 0; j < 4; ++j) {
                float q = (j == 0) ? qv.x : (j == 1) ? qv.y
                        : (j == 2) ? qv.z : qv.w;
                ull q2 = dup2(q);
                fma2(acc2[r][0], q2, bA[j].x);
                fma2(acc2[r][1], q2, bA[j].y);
                fma2(acc2[r][2], q2, bB[j].x);
                fma2(acc2[r][3], q2, bB[j].y);
            }
        }
    }

    if (ti == tj) {
        #pragma unroll
        for (int r = 0; r < 8; ++r) {
            float* orow = outTile + (size_t)(8 * ty + r) * L_SEQ;
            float2 p0 = unpack2(acc2[r][0]);
            float2 p1 = unpack2(acc2[r][1]);
            float2 p2 = unpack2(acc2[r][2]);
            float2 p3 = unpack2(acc2[r][3]);
            ((float4*)orow)[tx]        = make_float4(p0.x, p0.y, p1.x, p1.y);
            ((float4*)(orow + 64))[tx] = make_float4(p2.x, p2.y, p3.x, p3.y);
        }
        return;
    }

    // |ti-tj| == 1: partial band, mask per element
    const int gi0 = ti * TILE + 8 * ty;
    const int jA0 = tj * TILE + 4 * tx;
    const int jB0 = tj * TILE + 64 + 4 * tx;

    #pragma unroll
    for (int r = 0; r < 8; ++r) {
        const int gi = gi0 + r;
        float* orow = outTile + (size_t)(8 * ty + r) * L_SEQ;

        float2 p0 = unpack2(acc2[r][0]);
        float2 p1 = unpack2(acc2[r][1]);
        float2 p2 = unpack2(acc2[r][2]);
        float2 p3 = unpack2(acc2[r][3]);

        float4 vA, vB;
        {
            int d0 = gi - (jA0 + 0); if (d0 < 0) d0 = -d0;
            int d1 = gi - (jA0 + 1); if (d1 < 0) d1 = -d1;
            int d2 = gi - (jA0 + 2); if (d2 < 0) d2 = -d2;
            int d3 = gi - (jA0 + 3); if (d3 < 0) d3 = -d3;
            vA.x = (d0 <= R_BAND) ? p0.x : 0.f;
            vA.y = (d1 <= R_BAND) ? p0.y : 0.f;
            vA.z = (d2 <= R_BAND) ? p1.x : 0.f;
            vA.w = (d3 <= R_BAND) ? p1.y : 0.f;
        }
        {
            int d0 = gi - (jB0 + 0); if (d0 < 0) d0 = -d0;
            int d1 = gi - (jB0 + 1); if (d1 < 0) d1 = -d1;
            int d2 = gi - (jB0 + 2); if (d2 < 0) d2 = -d2;
            int d3 = gi - (jB0 + 3); if (d3 < 0) d3 = -d3;
            vB.x = (d0 <= R_BAND) ? p2.x : 0.f;
            vB.y = (d1 <= R_BAND) ? p2.y : 0.f;
            vB.z = (d2 <= R_BAND) ? p3.x : 0.f;
            vB.w = (d3 <= R_BAND) ? p3.y : 0.f;
        }

        ((float4*)orow)[tx]        = vA;
        ((float4*)(orow + 64))[tx] = vB;
    }
}

extern "C" void kernel_launch(void* const* d_in, const int* in_sizes, int n_in,
                              void* d_out, int out_size)
{
    const float* Q  = (const float*)d_in[0];
    const float* K  = (const float*)d_in[1];
    float*       out = (float*)d_out;

    const int smem_bytes = TILE * 16 * 16 + 64 * KT_S * 4;  // 66560

    cudaFuncSetAttribute(band_scores_kernel,
                         cudaFuncAttributeMaxDynamicSharedMemorySize,
                         smem_bytes);

    // R13 structure: fill and band fully concurrent (disjoint regions).
    // Streams/events created per call and leaked (capture-safe, no device
    // memory allocation — R13 precedent).
    cudaStream_t s2;
    cudaStreamCreateWithFlags(&s2, cudaStreamNonBlocking);
    cudaEvent_t e_fork, e_join;
    cudaEventCreateWithFlags(&e_fork, cudaEventDisableTiming);
    cudaEventCreateWithFlags(&e_join, cudaEventDisableTiming);

    cudaEventRecord(e_fork, 0);
    cudaStreamWaitEvent(s2, e_fork, 0);

    zero_fill_stg<<<FILL_CTAS, 256, 0, s2>>>(out);
    band_scores_kernel<<<N_BAND, 256, smem_bytes>>>(Q, K, out);

    cudaEventRecord(e_join, s2);
    cudaStreamWaitEvent(0, e_join, 0);
}